// round 14
// baseline (speedup 1.0000x reference)
#include <cuda_runtime.h>

#define NQ    12
#define DEPTH 6
#define TPB   128
#define MAXP  18

typedef unsigned int u32;

// ---------------------------------------------------------------------------
// Wire q <-> flat-index bit (11-q). CNOT ring = GF(2)-linear index map F.
// Frame-free storage: sv[swz(r)] holds raw index r. After d rings, the
// layer-d gate on bit m is the generalized-qubit gate
//   v = F^d e_m (pairing direction),  f = row m of F^{-d} (selection functional)
// Measurement after ring 6: logical index of raw r is F^{-6} r.
// Gates (v1,f1),(v2,f2) commute iff f1(v2)=0 and f2(v1)=0.
// ---------------------------------------------------------------------------
__host__ __device__ constexpr u32 Fmap(u32 b) {
    for (int g = 11; g >= 0; --g) {
        int c = 11 - g, t = (c + 11) % NQ;
        b ^= ((b >> c) & 1u) << t;
    }
    return b;
}
__host__ __device__ constexpr u32 Finvmap(u32 b) {
    for (int g = 0; g < NQ; ++g) {
        int c = 11 - g, t = (c + 11) % NQ;
        b ^= ((b >> c) & 1u) << t;
    }
    return b;
}
__host__ __device__ constexpr u32 swz(u32 x) { return x ^ ((x >> 5) & 31u); }
__host__ __device__ constexpr int par(u32 x) {
    x ^= x >> 16; x ^= x >> 8; x ^= x >> 4; x ^= x >> 2; x ^= x >> 1;
    return (int)(x & 1u);
}
__host__ __device__ constexpr u32 W6(u32 x) {
    for (int i = 0; i < 6; ++i) x = Finvmap(x);
    return x;
}

struct Elim {
    u32 rows[12]; int n;
    __host__ __device__ constexpr Elim() : rows{}, n(0) {}
    __host__ __device__ constexpr bool add(u32 v) {
        for (int i = 0; i < n; ++i) {
            u32 r = rows[i], hb = 1u << 11;
            while (!(r & hb)) hb >>= 1;
            if (v & hb) v ^= r;
        }
        if (!v) return false;
        rows[n++] = v;
        return true;
    }
};

struct Sched {
    int npass;
    int cnt[MAXP];
    int gidx[MAXP][5];
    u32 gdir[MAXP][5];
    u32 fill[MAXP][7];
    u32 wdir[5];
    u32 wfill[7];
};
__host__ __device__ constexpr Sched mk_sched() {
    Sched S{};
    u32 V[6][12] = {}, FN[6][12] = {}, IC[6][12] = {};
    for (int m = 0; m < 12; ++m) V[0][m] = 1u << m;
    for (int d = 1; d < 6; ++d)
        for (int m = 0; m < 12; ++m) V[d][m] = Fmap(V[d-1][m]);
    for (int j = 0; j < 12; ++j) IC[0][j] = 1u << j;
    for (int d = 1; d < 6; ++d)
        for (int j = 0; j < 12; ++j) IC[d][j] = Finvmap(IC[d-1][j]);
    for (int d = 1; d < 6; ++d)
        for (int m = 0; m < 12; ++m) {
            u32 fv = 0;
            for (int j = 0; j < 12; ++j)
                if ((IC[d][j] >> m) & 1u) fv |= 1u << j;   // (F^{-d})_{m,j}
            FN[d][m] = fv;
        }
    bool used[6][12] = {};
    int remaining = 60, P = 0;
    u32 lastreg[5] = {}, lastfill[7] = {};
    while (remaining > 0) {                   // P>=MAXP -> constexpr OOB error
        Elim E;
        u32 pv[5] = {}, pf[5] = {};
        int c = 0;
        for (int d = 1; d < 6 && c < 5; ++d)
            for (int m = 11; m >= 0 && c < 5; --m) {
                if (used[d][m]) continue;
                u32 v = V[d][m], f = FN[d][m];
                bool ok = true;
                for (int i = 0; i < c; ++i)
                    if (par(pf[i] & v) || par(f & pv[i])) { ok = false; break; }
                if (ok)
                    for (int d2 = 1; d2 < d && ok; ++d2)
                        for (int m2 = 0; m2 < 12 && ok; ++m2)
                            if (!used[d2][m2] &&
                                (par(FN[d2][m2] & v) || par(f & V[d2][m2])))
                                ok = false;
                if (!ok) continue;
                if (!E.add(v)) continue;
                used[d][m] = true; --remaining;
                pv[c] = v; pf[c] = f;
                S.gidx[P][c] = d * NQ + m;
                S.gdir[P][c] = swz(v);
                ++c;
            }
        S.cnt[P] = c;
        // null space of the c functionals (RREF + free columns)
        u32 R[5] = {};
        for (int i = 0; i < c; ++i) R[i] = pf[i];
        int pivcol[5] = {}; bool ispiv[12] = {}; int nrows = 0;
        for (int col = 0; col < 12 && nrows < c; ++col) {
            int sel = -1;
            for (int r = nrows; r < c; ++r)
                if ((R[r] >> col) & 1u) { sel = r; break; }
            if (sel < 0) continue;
            u32 tmp = R[nrows]; R[nrows] = R[sel]; R[sel] = tmp;
            for (int r = 0; r < c; ++r)
                if (r != nrows && ((R[r] >> col) & 1u)) R[r] ^= R[nrows];
            pivcol[nrows] = col; ispiv[col] = true; ++nrows;
        }
        u32 ns[12] = {}; int nn = 0;
        for (int j = 0; j < 12; ++j) {
            if (ispiv[j]) continue;
            u32 x = 1u << j;
            for (int r = 0; r < nrows; ++r)
                if ((R[r] >> j) & 1u) x |= 1u << pivcol[r];
            ns[nn++] = x;
        }
        u32 regraw[5] = {};
        for (int i = 0; i < c; ++i) regraw[i] = pv[i];
        int k = 0;
        for (int i = c; i < 5; ++i) { regraw[i] = ns[k]; S.gdir[P][i] = swz(ns[k]); ++k; }
        u32 fillraw[7] = {};
        for (int j = 0; j < 7; ++j) { fillraw[j] = ns[k]; S.fill[P][j] = swz(ns[k]); ++k; }
        for (int i = 0; i < 5; ++i) lastreg[i] = regraw[i];
        for (int j = 0; j < 7; ++j) lastfill[j] = fillraw[j];
        ++P;
    }
    S.npass = P;
    for (int i = 0; i < 5; ++i) S.wdir[i]  = W6(lastreg[i]);
    for (int j = 0; j < 7; ++j) S.wfill[j] = W6(lastfill[j]);
    return S;
}
constexpr Sched HS = mk_sched();
constexpr int   NP = HS.npass;

__device__ __forceinline__ float2 cmul(float2 a, float2 b) {
    return make_float2(fmaf(a.x, b.x, -a.y * b.y), fmaf(a.x, b.y, a.y * b.x));
}

// SU(2) gate on register bit BIT across the 32-amp slot array.
template<int BIT>
__device__ __forceinline__ void gate5(float2 (&s)[32], float2 u, float2 v) {
    #pragma unroll
    for (int c = 0; c < 32; ++c) {
        if (!((c >> BIT) & 1)) {
            float2 a0 = s[c], a1 = s[c | (1 << BIT)];
            float2 n0, n1;
            n0.x = fmaf(u.x, a0.x, fmaf(-u.y, a0.y, fmaf(v.x, a1.x, -v.y * a1.y)));
            n0.y = fmaf(u.x, a0.y, fmaf( u.y, a0.x, fmaf(v.x, a1.y,  v.y * a1.x)));
            n1.x = fmaf(u.x, a1.x, fmaf( u.y, a1.y, fmaf(-v.x, a0.x, -v.y * a0.y)));
            n1.y = fmaf(u.x, a1.y, fmaf(-u.y, a1.x, fmaf( v.y, a0.x, -v.x * a0.y)));
            s[c] = n0; s[c | (1 << BIT)] = n1;
        }
    }
}

template<int P>
__device__ __forceinline__ void do_pass(int t, float2* sv, const float2* gms,
                                        float& acc) {
    // ---- all schedule data extracted as constexpr SCALARS (no HS pointers) --
    constexpr u32 F0 = HS.fill[P][0], F1 = HS.fill[P][1], F2 = HS.fill[P][2],
                  F3 = HS.fill[P][3], F4 = HS.fill[P][4], F5 = HS.fill[P][5],
                  F6 = HS.fill[P][6];
    constexpr u32 Q0 = HS.gdir[P][0], Q1 = HS.gdir[P][1], Q2 = HS.gdir[P][2],
                  Q3 = HS.gdir[P][3], Q4 = HS.gdir[P][4];
    constexpr int CP   = HS.cnt[P];
    constexpr bool LAST = (P == NP - 1);

    u32 pb = ((t >> 0 & 1) ? F0 : 0u) ^ ((t >> 1 & 1) ? F1 : 0u)
           ^ ((t >> 2 & 1) ? F2 : 0u) ^ ((t >> 3 & 1) ? F3 : 0u)
           ^ ((t >> 4 & 1) ? F4 : 0u) ^ ((t >> 5 & 1) ? F5 : 0u)
           ^ ((t >> 6 & 1) ? F6 : 0u);

    float2 s[32];
    #pragma unroll
    for (int c = 0; c < 32; ++c) {
        u32 off = ((c & 1)  ? Q0 : 0u) ^ ((c & 2)  ? Q1 : 0u)
                ^ ((c & 4)  ? Q2 : 0u) ^ ((c & 8)  ? Q3 : 0u)
                ^ ((c & 16) ? Q4 : 0u);            // folds to immediate per c
        s[c] = sv[pb ^ off];
    }

    if constexpr (CP > 0) {
        constexpr int GI = HS.gidx[P][0];
        gate5<0>(s, gms[GI * 2], gms[GI * 2 + 1]);
    }
    if constexpr (CP > 1) {
        constexpr int GI = HS.gidx[P][1];
        gate5<1>(s, gms[GI * 2], gms[GI * 2 + 1]);
    }
    if constexpr (CP > 2) {
        constexpr int GI = HS.gidx[P][2];
        gate5<2>(s, gms[GI * 2], gms[GI * 2 + 1]);
    }
    if constexpr (CP > 3) {
        constexpr int GI = HS.gidx[P][3];
        gate5<3>(s, gms[GI * 2], gms[GI * 2 + 1]);
    }
    if constexpr (CP > 4) {
        constexpr int GI = HS.gidx[P][4];
        gate5<4>(s, gms[GI * 2], gms[GI * 2 + 1]);
    }

    if constexpr (LAST) {
        constexpr u32 W0 = HS.wfill[0], W1 = HS.wfill[1], W2 = HS.wfill[2],
                      W3 = HS.wfill[3], W4 = HS.wfill[4], W5 = HS.wfill[5],
                      W6m = HS.wfill[6];
        constexpr u32 D0 = HS.wdir[0], D1 = HS.wdir[1], D2 = HS.wdir[2],
                      D3 = HS.wdir[3], D4 = HS.wdir[4];
        u32 fb = ((t >> 0 & 1) ? W0 : 0u) ^ ((t >> 1 & 1) ? W1 : 0u)
               ^ ((t >> 2 & 1) ? W2 : 0u) ^ ((t >> 3 & 1) ? W3 : 0u)
               ^ ((t >> 4 & 1) ? W4 : 0u) ^ ((t >> 5 & 1) ? W5 : 0u)
               ^ ((t >> 6 & 1) ? W6m : 0u);
        #pragma unroll
        for (int c = 0; c < 32; ++c) {
            u32 woff = ((c & 1)  ? D0 : 0u) ^ ((c & 2)  ? D1 : 0u)
                     ^ ((c & 4)  ? D2 : 0u) ^ ((c & 8)  ? D3 : 0u)
                     ^ ((c & 16) ? D4 : 0u);       // folds to immediate per c
            float wgt = (float)(NQ - 2 * __popc(fb ^ woff));
            acc = fmaf(fmaf(s[c].x, s[c].x, s[c].y * s[c].y), wgt, acc);
        }
    } else {
        #pragma unroll
        for (int c = 0; c < 32; ++c) {
            u32 off = ((c & 1)  ? Q0 : 0u) ^ ((c & 2)  ? Q1 : 0u)
                    ^ ((c & 4)  ? Q2 : 0u) ^ ((c & 8)  ? Q3 : 0u)
                    ^ ((c & 16) ? Q4 : 0u);
            sv[pb ^ off] = s[c];
        }
        __syncthreads();
    }
}

template<int P>
__device__ __forceinline__ void run_passes(int t, float2* sv, const float2* gms,
                                           float& acc) {
    if constexpr (P < NP) {
        do_pass<P>(t, sv, gms, acc);
        run_passes<P + 1>(t, sv, gms, acc);
    }
}

__global__ void __launch_bounds__(TPB, 4)
qsim_kernel(const float* __restrict__ inp, const float* __restrict__ wp,
            float* __restrict__ out)
{
    __shared__ float2 sv[1 << NQ];               // 32 KB state
    __shared__ float2 gms[DEPTH * NQ * 2];       // m00,m01 per gate (SU(2))
    __shared__ float2 vtab[NQ][2];               // per-qubit prep 2-vectors
    __shared__ float  red[TPB / 32];

    const int t   = threadIdx.x;
    const int bid = blockIdx.x;

    // ---- per-block prep ----------------------------------------------------
    if (t < NQ) {
        // fold encode RY(x) with layer-1 Rot into one complex 2-vector/qubit
        float x = inp[bid * NQ + (11 - t)];      // bit t <- wire 11-t
        float sx, cx; sincosf(0.5f * x, &sx, &cx);
        int wo = (11 - t) * 3;                   // w[0][wire]
        float phi = wp[wo + 0], th = wp[wo + 1], om = wp[wo + 2];
        float st, ct; sincosf(0.5f * th, &st, &ct);
        float sa, ca; sincosf(0.5f * (phi + om), &sa, &ca);
        float sb, cb; sincosf(0.5f * (phi - om), &sb, &cb);
        float2 m00 = make_float2( ct * ca, -ct * sa);
        float2 m01 = make_float2(-st * cb, -st * sb);
        float2 m10 = make_float2( st * cb, -st * sb);   // = -conj(m01)
        float2 m11 = make_float2( ct * ca,  ct * sa);   // =  conj(m00)
        vtab[t][0] = make_float2(fmaf(m00.x, cx, m01.x * sx), fmaf(m00.y, cx, m01.y * sx));
        vtab[t][1] = make_float2(fmaf(m10.x, cx, m11.x * sx), fmaf(m10.y, cx, m11.y * sx));
    } else if (t < DEPTH * NQ) {
        // gate matrices for layers 2..6 (d = 1..5); SU(2): keep m00,m01 only
        int d = t / NQ, m = t % NQ;              // m = bit index, wire = 11-m
        int wo = (d * NQ + (11 - m)) * 3;
        float phi = wp[wo + 0], th = wp[wo + 1], om = wp[wo + 2];
        float st, ct; sincosf(0.5f * th, &st, &ct);
        float sa, ca; sincosf(0.5f * (phi + om), &sa, &ca);
        float sb, cb; sincosf(0.5f * (phi - om), &sb, &cb);
        gms[t * 2 + 0] = make_float2( ct * ca, -ct * sa);   // m00
        gms[t * 2 + 1] = make_float2(-st * cb, -st * sb);   // m01
    }
    __syncthreads();

    // ---- prep pass: psi_1 (encode + layer-1 Rot) in identity frame ---------
    {
        u32 pb = 0;
        #pragma unroll
        for (int j = 0; j < 7; ++j)
            if ((t >> j) & 1) pb ^= swz(1u << (5 + j));
        float2 f = vtab[5][t & 1];
        #pragma unroll
        for (int j = 1; j < 7; ++j) f = cmul(f, vtab[5 + j][(t >> j) & 1]);
        float2 v[32]; v[0] = f;
        #pragma unroll
        for (int j = 0; j < 5; ++j) {
            #pragma unroll
            for (int k = 0; k < (1 << j); ++k) {
                float2 lo = v[k];
                v[k]            = cmul(lo, vtab[j][0]);
                v[k + (1 << j)] = cmul(lo, vtab[j][1]);
            }
        }
        #pragma unroll
        for (int c = 0; c < 32; ++c) {
            u32 a = pb;
            if (c & 1)  a ^= swz(1u << 0);
            if (c & 2)  a ^= swz(1u << 1);
            if (c & 4)  a ^= swz(1u << 2);
            if (c & 8)  a ^= swz(1u << 3);
            if (c & 16) a ^= swz(1u << 4);
            sv[a] = v[c];
        }
        __syncthreads();
    }

    float acc = 0.f;
    run_passes<0>(t, sv, gms, acc);

    // ---- block reduction -> out[bid] ----
    #pragma unroll
    for (int o = 16; o; o >>= 1) acc += __shfl_xor_sync(0xffffffffu, acc, o);
    if ((t & 31) == 0) red[t >> 5] = acc;
    __syncthreads();
    if (t == 0)
        out[bid] = (red[0] + red[1] + red[2] + red[3]) * (1.0f / NQ);
}

extern "C" void kernel_launch(void* const* d_in, const int* in_sizes, int n_in,
                              void* d_out, int out_size)
{
    const float *inp, *wp;
    if (in_sizes[0] == DEPTH * NQ * 3) {            // defensive input-order check
        wp  = (const float*)d_in[0];
        inp = (const float*)d_in[1];
    } else {
        inp = (const float*)d_in[0];
        wp  = (const float*)d_in[1];
    }
    int B = out_size;                                // [B,1] float output
    qsim_kernel<<<B, TPB>>>(inp, wp, (float*)d_out);
}

// round 15
// speedup vs baseline: 1.2949x; 1.2949x over previous
#include <cuda_runtime.h>

#define NQ    12
#define DEPTH 6
#define TPB   128

typedef unsigned int u32;

// ---------------------------------------------------------------------------
// Wire q <-> flat-index bit (11-q). CNOT ring tracked as GF(2)-linear storage
// permutation; Q_d = F^d columns precomputed (with smem swizzle composed in).
// Rot(phi,theta,omega) = D_l(omega) * RY(theta) * D_r(phi): the diagonals act
// on each pass's register bits only -> per-slot phasor tables Pre/Post.
// Layer-6 D_l commutes through the final ring (a basis permutation) and is
// invisible to |amp|^2 -> dropped.
// ---------------------------------------------------------------------------
__host__ __device__ constexpr u32 Fmap(u32 b) {
    for (int g = 11; g >= 0; --g) {
        int c = 11 - g, t = (c + 11) % NQ;
        b ^= ((b >> c) & 1u) << t;
    }
    return b;
}
__host__ __device__ constexpr u32 Finvmap(u32 b) {
    for (int g = 0; g < NQ; ++g) {
        int c = 11 - g, t = (c + 11) % NQ;
        b ^= ((b >> c) & 1u) << t;
    }
    return b;
}
__host__ __device__ constexpr u32 swz(u32 x) { return x ^ ((x >> 5) & 31u); }

struct Tabs {
    u32 q[DEPTH][NQ];  // swizzled columns of Q_d = F^d
    u32 finv[NQ];      // columns of F^{-1} (logical space, for final weights)
};
__host__ __device__ constexpr Tabs mk_tabs() {
    Tabs t{};
    u32 raw[NQ] = {};
    for (int j = 0; j < NQ; ++j) { raw[j] = 1u << j; t.q[0][j] = swz(raw[j]); }
    for (int d = 1; d < DEPTH; ++d)
        for (int j = 0; j < NQ; ++j) { raw[j] = Fmap(raw[j]); t.q[d][j] = swz(raw[j]); }
    for (int j = 0; j < NQ; ++j) t.finv[j] = Finvmap(1u << j);
    return t;
}
__constant__ Tabs TAB = mk_tabs();

// Pass p owns 5 bit-directions (gates on first 4); filler bits from tid.
__constant__ int DIRS[3][5] = {{0,1,2,3,4},{4,5,6,7,8},{8,9,10,11,0}};
__constant__ int FILL[3][7] = {{5,6,7,8,9,10,11},{0,1,2,3,9,10,11},{1,2,3,4,5,6,7}};

__device__ __forceinline__ float2 cmul(float2 a, float2 b) {
    return make_float2(fmaf(a.x, b.x, -a.y * b.y), fmaf(a.x, b.y, a.y * b.x));
}

__global__ void __launch_bounds__(TPB, 4)
qsim_kernel(const float* __restrict__ inp, const float* __restrict__ wp,
            float* __restrict__ out)
{
    __shared__ float2 sv[1 << NQ];               // 32 KB state (AoS re,im)
    __shared__ float2 gry[DEPTH * NQ];           // (cos,sin) of theta/2 per gate
    __shared__ float2 PreT[15 * 16];             // D_r phasors per (d,p) slot
    __shared__ float2 PostT[12 * 16];            // D_l phasors (layers 2..5 only)
    __shared__ float2 vtab[NQ][2];               // per-qubit prep 2-vectors
    __shared__ float  red[TPB / 32];

    const int t   = threadIdx.x;
    const int bid = blockIdx.x;

    // ---- per-block prep ----------------------------------------------------
    if (t < NQ) {
        // fold encode RY(x) with layer-1 Rot into one complex 2-vector/qubit
        float x = inp[bid * NQ + (11 - t)];      // bit t <- wire 11-t
        float sx, cx; sincosf(0.5f * x, &sx, &cx);
        int wo = (11 - t) * 3;                   // w[0][wire]
        float phi = wp[wo + 0], th = wp[wo + 1], om = wp[wo + 2];
        float st, ct; sincosf(0.5f * th, &st, &ct);
        float sa, ca; sincosf(0.5f * (phi + om), &sa, &ca);
        float sb, cb; sincosf(0.5f * (phi - om), &sb, &cb);
        float2 m00 = make_float2( ct * ca, -ct * sa);
        float2 m01 = make_float2(-st * cb, -st * sb);
        float2 m10 = make_float2( st * cb, -st * sb);   // = -conj(m01)
        float2 m11 = make_float2( ct * ca,  ct * sa);   // =  conj(m00)
        vtab[t][0] = make_float2(fmaf(m00.x, cx, m01.x * sx), fmaf(m00.y, cx, m01.y * sx));
        vtab[t][1] = make_float2(fmaf(m10.x, cx, m11.x * sx), fmaf(m10.y, cx, m11.y * sx));
    } else if (t < DEPTH * NQ) {
        // RY core for layers 2..6 (d = 1..5)
        int d = t / NQ, m = t % NQ;              // m = bit index, wire = 11-m
        float th = wp[(d * NQ + (11 - m)) * 3 + 1];
        float st, ct; sincosf(0.5f * th, &st, &ct);
        gry[t] = make_float2(ct, st);
    }
    // diagonal phasor tables: Pre (15 dp x 16) then Post (12 dp x 16)
    for (int e = t; e < 27 * 16; e += TPB) {
        bool isPre = e < 240;
        int ee = isPre ? e : e - 240;
        int dp = ee >> 4, c = ee & 15;
        int d = dp / 3 + 1, p = dp % 3;
        float ang = 0.f;
        #pragma unroll
        for (int g = 0; g < 4; ++g) {
            int m = p * 4 + g;
            float a = wp[(d * NQ + (11 - m)) * 3 + (isPre ? 0 : 2)];
            ang += ((c >> g) & 1) ? 0.5f * a : -0.5f * a;
        }
        float sn, cs; sincosf(ang, &sn, &cs);
        if (isPre) PreT[ee]  = make_float2(cs, sn);
        else       PostT[ee] = make_float2(cs, sn);
    }
    __syncthreads();

    // ---- prep pass: build psi_1 (encode + layer-1 Rot) and store ----------
    {
        const u32* qc = TAB.q[0];
        u32 pb = 0;
        #pragma unroll
        for (int j = 0; j < 7; ++j)
            if ((t >> j) & 1) pb ^= qc[FILL[0][j]];     // logical bits 5..11
        u32 qd[5];
        #pragma unroll
        for (int k = 0; k < 5; ++k) qd[k] = qc[DIRS[0][k]];

        float2 f = vtab[5][t & 1];
        #pragma unroll
        for (int j = 1; j < 7; ++j) f = cmul(f, vtab[5 + j][(t >> j) & 1]);
        float2 v[32]; v[0] = f;
        #pragma unroll
        for (int j = 0; j < 5; ++j) {
            #pragma unroll
            for (int k = 0; k < (1 << j); ++k) {
                float2 lo = v[k];
                v[k]            = cmul(lo, vtab[j][0]);
                v[k + (1 << j)] = cmul(lo, vtab[j][1]);
            }
        }
        #pragma unroll
        for (int c = 0; c < 32; ++c) {
            u32 a = pb;
            if (c & 1)  a ^= qd[0];
            if (c & 2)  a ^= qd[1];
            if (c & 4)  a ^= qd[2];
            if (c & 8)  a ^= qd[3];
            if (c & 16) a ^= qd[4];
            sv[a] = v[c];
        }
        __syncthreads();
    }

    float acc = 0.f;

    // ---- variational layers 2..6 -------------------------------------------
    for (int d = 1; d < DEPTH; ++d) {
        const u32* qc = TAB.q[d];
        for (int p = 0; p < 3; ++p) {
            const int dp = (d - 1) * 3 + p;
            u32 pb = 0;
            #pragma unroll
            for (int j = 0; j < 7; ++j)
                if ((t >> j) & 1) pb ^= qc[FILL[p][j]];
            u32 qd[5];
            #pragma unroll
            for (int k = 0; k < 5; ++k) qd[k] = qc[DIRS[p][k]];

            // gather + D_r (Pre) multiply
            float2 s[32];
            #pragma unroll
            for (int c = 0; c < 32; ++c) {
                u32 a = pb;
                if (c & 1)  a ^= qd[0];
                if (c & 2)  a ^= qd[1];
                if (c & 4)  a ^= qd[2];
                if (c & 8)  a ^= qd[3];
                if (c & 16) a ^= qd[4];
                s[c] = cmul(sv[a], PreT[dp * 16 + (c & 15)]);
            }

            // ---- 4 register-resident REAL RY gates on bits p*4..p*4+3 ------
            #pragma unroll
            for (int g = 0; g < 4; ++g) {
                float2 cs = gry[d * NQ + p * 4 + g];
                float cg = cs.x, sg = cs.y;
                #pragma unroll
                for (int c = 0; c < 32; ++c) {
                    if (!((c >> g) & 1)) {
                        float2 a0 = s[c], a1 = s[c | (1 << g)];
                        float2 n0, n1;
                        n0.x = fmaf(-sg, a1.x, cg * a0.x);
                        n0.y = fmaf(-sg, a1.y, cg * a0.y);
                        n1.x = fmaf( cg, a1.x, sg * a0.x);
                        n1.y = fmaf( cg, a1.y, sg * a0.y);
                        s[c] = n0; s[c | (1 << g)] = n1;
                    }
                }
            }

            if (d == DEPTH - 1 && p == 2) {
                // ---- fold final ring + <Z> mean into the reduction ---------
                // (layer-6 D_l dropped: diagonal, invisible to |amp|^2)
                u32 fb = 0;
                #pragma unroll
                for (int j = 0; j < 7; ++j)
                    if ((t >> j) & 1) fb ^= TAB.finv[FILL[2][j]];
                u32 fd[5];
                #pragma unroll
                for (int k = 0; k < 5; ++k) fd[k] = TAB.finv[DIRS[2][k]];
                #pragma unroll
                for (int c = 0; c < 32; ++c) {
                    u32 fv = fb;
                    if (c & 1)  fv ^= fd[0];
                    if (c & 2)  fv ^= fd[1];
                    if (c & 4)  fv ^= fd[2];
                    if (c & 8)  fv ^= fd[3];
                    if (c & 16) fv ^= fd[4];
                    float wgt = (float)(NQ - 2 * __popc(fv));
                    acc = fmaf(fmaf(s[c].x, s[c].x, s[c].y * s[c].y), wgt, acc);
                }
            } else {
                // D_l (Post) multiply + scatter (skip Post for layer 6)
                const bool lastLayer = (d == DEPTH - 1);
                #pragma unroll
                for (int c = 0; c < 32; ++c) {
                    float2 vv = lastLayer ? s[c]
                              : cmul(s[c], PostT[dp * 16 + (c & 15)]);
                    u32 a = pb;
                    if (c & 1)  a ^= qd[0];
                    if (c & 2)  a ^= qd[1];
                    if (c & 4)  a ^= qd[2];
                    if (c & 8)  a ^= qd[3];
                    if (c & 16) a ^= qd[4];
                    sv[a] = vv;
                }
                __syncthreads();
            }
        }
    }

    // ---- block reduction -> out[bid] ----
    #pragma unroll
    for (int o = 16; o; o >>= 1) acc += __shfl_xor_sync(0xffffffffu, acc, o);
    if ((t & 31) == 0) red[t >> 5] = acc;
    __syncthreads();
    if (t == 0)
        out[bid] = (red[0] + red[1] + red[2] + red[3]) * (1.0f / NQ);
}

extern "C" void kernel_launch(void* const* d_in, const int* in_sizes, int n_in,
                              void* d_out, int out_size)
{
    const float *inp, *wp;
    if (in_sizes[0] == DEPTH * NQ * 3) {            // defensive input-order check
        wp  = (const float*)d_in[0];
        inp = (const float*)d_in[1];
    } else {
        inp = (const float*)d_in[0];
        wp  = (const float*)d_in[1];
    }
    int B = out_size;                                // [B,1] float output
    qsim_kernel<<<B, TPB>>>(inp, wp, (float*)d_out);
}

// round 17
// speedup vs baseline: 1.3119x; 1.0131x over previous
#include <cuda_runtime.h>

#define NQ    12
#define DEPTH 6
#define TPB   128

typedef unsigned int u32;

// ---------------------------------------------------------------------------
// Wire q <-> flat-index bit (11-q). CNOT ring tracked as GF(2)-linear storage
// permutation; Q_d = F^d columns precomputed (with smem swizzle composed in).
// Rot(phi,theta,omega) = D_l(omega) * RY(theta) * D_r(phi): the diagonals act
// on each pass's register bits only -> per-slot phasor tables Pre/Post.
// Layer-6 D_l commutes through the final ring (a basis permutation) and is
// invisible to |amp|^2 -> dropped.
// RY core applied via lifting (3 shears): [c -s; s c] =
// [1 k;0 1][1 0;s 1][1 k;0 1], k = -tan(theta/4)  -> 3 FMA/component-pair.
// ---------------------------------------------------------------------------
__host__ __device__ constexpr u32 Fmap(u32 b) {
    for (int g = 11; g >= 0; --g) {
        int c = 11 - g, t = (c + 11) % NQ;
        b ^= ((b >> c) & 1u) << t;
    }
    return b;
}
__host__ __device__ constexpr u32 Finvmap(u32 b) {
    for (int g = 0; g < NQ; ++g) {
        int c = 11 - g, t = (c + 11) % NQ;
        b ^= ((b >> c) & 1u) << t;
    }
    return b;
}
__host__ __device__ constexpr u32 swz(u32 x) { return x ^ ((x >> 5) & 31u); }

struct Tabs {
    u32 q[DEPTH][NQ];  // swizzled columns of Q_d = F^d
    u32 finv[NQ];      // columns of F^{-1} (logical space, for final weights)
};
__host__ __device__ constexpr Tabs mk_tabs() {
    Tabs t{};
    u32 raw[NQ] = {};
    for (int j = 0; j < NQ; ++j) { raw[j] = 1u << j; t.q[0][j] = swz(raw[j]); }
    for (int d = 1; d < DEPTH; ++d)
        for (int j = 0; j < NQ; ++j) { raw[j] = Fmap(raw[j]); t.q[d][j] = swz(raw[j]); }
    for (int j = 0; j < NQ; ++j) t.finv[j] = Finvmap(1u << j);
    return t;
}
__constant__ Tabs TAB = mk_tabs();

// Pass p owns 5 bit-directions (gates on first 4); filler bits from tid.
__constant__ int DIRS[3][5] = {{0,1,2,3,4},{4,5,6,7,8},{8,9,10,11,0}};
__constant__ int FILL[3][7] = {{5,6,7,8,9,10,11},{0,1,2,3,9,10,11},{1,2,3,4,5,6,7}};

__device__ __forceinline__ float2 cmul(float2 a, float2 b) {
    return make_float2(fmaf(a.x, b.x, -a.y * b.y), fmaf(a.x, b.y, a.y * b.x));
}

__global__ void __launch_bounds__(TPB, 4)
qsim_kernel(const float* __restrict__ inp, const float* __restrict__ wp,
            float* __restrict__ out)
{
    __shared__ float2 sv[1 << NQ];               // 32 KB state (AoS re,im)
    __shared__ float2 gry[DEPTH * NQ];           // (k=-tan(th/4), s=sin(th/2))
    __shared__ float2 PreT[15 * 16];             // D_r phasors per (d,p) slot
    __shared__ float2 PostT[12 * 16];            // D_l phasors (layers 2..5 only)
    __shared__ float2 vtab[NQ][2];               // per-qubit prep 2-vectors
    __shared__ float  red[TPB / 32];

    const int t   = threadIdx.x;
    const int bid = blockIdx.x;

    // ---- per-block prep ----------------------------------------------------
    if (t < NQ) {
        // fold encode RY(x) with layer-1 Rot into one complex 2-vector/qubit
        float x = inp[bid * NQ + (11 - t)];      // bit t <- wire 11-t
        float sx, cx; sincosf(0.5f * x, &sx, &cx);
        int wo = (11 - t) * 3;                   // w[0][wire]
        float phi = wp[wo + 0], th = wp[wo + 1], om = wp[wo + 2];
        float st, ct; sincosf(0.5f * th, &st, &ct);
        float sa, ca; sincosf(0.5f * (phi + om), &sa, &ca);
        float sb, cb; sincosf(0.5f * (phi - om), &sb, &cb);
        float2 m00 = make_float2( ct * ca, -ct * sa);
        float2 m01 = make_float2(-st * cb, -st * sb);
        float2 m10 = make_float2( st * cb, -st * sb);   // = -conj(m01)
        float2 m11 = make_float2( ct * ca,  ct * sa);   // =  conj(m00)
        vtab[t][0] = make_float2(fmaf(m00.x, cx, m01.x * sx), fmaf(m00.y, cx, m01.y * sx));
        vtab[t][1] = make_float2(fmaf(m10.x, cx, m11.x * sx), fmaf(m10.y, cx, m11.y * sx));
    } else if (t < DEPTH * NQ) {
        // RY lifting coefficients for layers 2..6 (d = 1..5)
        int d = t / NQ, m = t % NQ;              // m = bit index, wire = 11-m
        float th = wp[(d * NQ + (11 - m)) * 3 + 1];
        float k = -tanf(0.25f * th);
        float s = sinf(0.5f * th);
        gry[t] = make_float2(k, s);
    }
    // diagonal phasor tables: Pre (15 dp x 16) then Post (12 dp x 16)
    for (int e = t; e < 27 * 16; e += TPB) {
        bool isPre = e < 240;
        int ee = isPre ? e : e - 240;
        int dp = ee >> 4, c = ee & 15;
        int d = dp / 3 + 1, p = dp % 3;
        float ang = 0.f;
        #pragma unroll
        for (int g = 0; g < 4; ++g) {
            int m = p * 4 + g;
            float a = wp[(d * NQ + (11 - m)) * 3 + (isPre ? 0 : 2)];
            ang += ((c >> g) & 1) ? 0.5f * a : -0.5f * a;
        }
        float sn, cs; sincosf(ang, &sn, &cs);
        if (isPre) PreT[ee]  = make_float2(cs, sn);
        else       PostT[ee] = make_float2(cs, sn);
    }
    __syncthreads();

    // ---- prep pass: build psi_1 (encode + layer-1 Rot) and store ----------
    {
        const u32* qc = TAB.q[0];
        u32 pb = 0;
        #pragma unroll
        for (int j = 0; j < 7; ++j)
            if ((t >> j) & 1) pb ^= qc[FILL[0][j]];     // logical bits 5..11
        u32 qd[5];
        #pragma unroll
        for (int k = 0; k < 5; ++k) qd[k] = qc[DIRS[0][k]];

        float2 f = vtab[5][t & 1];
        #pragma unroll
        for (int j = 1; j < 7; ++j) f = cmul(f, vtab[5 + j][(t >> j) & 1]);
        float2 v[32]; v[0] = f;
        #pragma unroll
        for (int j = 0; j < 5; ++j) {
            #pragma unroll
            for (int k = 0; k < (1 << j); ++k) {
                float2 lo = v[k];
                v[k]            = cmul(lo, vtab[j][0]);
                v[k + (1 << j)] = cmul(lo, vtab[j][1]);
            }
        }
        #pragma unroll
        for (int c = 0; c < 32; ++c) {
            u32 a = pb;
            if (c & 1)  a ^= qd[0];
            if (c & 2)  a ^= qd[1];
            if (c & 4)  a ^= qd[2];
            if (c & 8)  a ^= qd[3];
            if (c & 16) a ^= qd[4];
            sv[a] = v[c];
        }
        __syncthreads();
    }

    float acc = 0.f;

    // ---- variational layers 2..6 -------------------------------------------
    for (int d = 1; d < DEPTH; ++d) {
        const u32* qc = TAB.q[d];
        for (int p = 0; p < 3; ++p) {
            const int dp = (d - 1) * 3 + p;
            u32 pb = 0;
            #pragma unroll
            for (int j = 0; j < 7; ++j)
                if ((t >> j) & 1) pb ^= qc[FILL[p][j]];
            u32 qd[5];
            #pragma unroll
            for (int k = 0; k < 5; ++k) qd[k] = qc[DIRS[p][k]];

            // gather + D_r (Pre) multiply
            float2 s[32];
            #pragma unroll
            for (int c = 0; c < 32; ++c) {
                u32 a = pb;
                if (c & 1)  a ^= qd[0];
                if (c & 2)  a ^= qd[1];
                if (c & 4)  a ^= qd[2];
                if (c & 8)  a ^= qd[3];
                if (c & 16) a ^= qd[4];
                s[c] = cmul(sv[a], PreT[dp * 16 + (c & 15)]);
            }

            // ---- 4 register-resident RY gates via lifting ------------------
            #pragma unroll
            for (int g = 0; g < 4; ++g) {
                float2 ks = gry[d * NQ + p * 4 + g];
                float kg = ks.x, sg = ks.y;
                #pragma unroll
                for (int c = 0; c < 32; ++c) {
                    if (!((c >> g) & 1)) {
                        float2 a0 = s[c], a1 = s[c | (1 << g)];
                        float tx = fmaf(kg, a1.x, a0.x);
                        float ty = fmaf(kg, a1.y, a0.y);
                        a1.x = fmaf(sg, tx, a1.x);
                        a1.y = fmaf(sg, ty, a1.y);
                        a0.x = fmaf(kg, a1.x, tx);
                        a0.y = fmaf(kg, a1.y, ty);
                        s[c] = a0; s[c | (1 << g)] = a1;
                    }
                }
            }

            if (d == DEPTH - 1 && p == 2) {
                // ---- fold final ring + <Z> mean into the reduction ---------
                // (layer-6 D_l dropped: diagonal, invisible to |amp|^2)
                u32 fb = 0;
                #pragma unroll
                for (int j = 0; j < 7; ++j)
                    if ((t >> j) & 1) fb ^= TAB.finv[FILL[2][j]];
                u32 fd[5];
                #pragma unroll
                for (int k = 0; k < 5; ++k) fd[k] = TAB.finv[DIRS[2][k]];
                #pragma unroll
                for (int c = 0; c < 32; ++c) {
                    u32 fv = fb;
                    if (c & 1)  fv ^= fd[0];
                    if (c & 2)  fv ^= fd[1];
                    if (c & 4)  fv ^= fd[2];
                    if (c & 8)  fv ^= fd[3];
                    if (c & 16) fv ^= fd[4];
                    float wgt = (float)(NQ - 2 * __popc(fv));
                    acc = fmaf(fmaf(s[c].x, s[c].x, s[c].y * s[c].y), wgt, acc);
                }
            } else {
                // D_l (Post) multiply + scatter (skip Post for layer 6)
                const bool lastLayer = (d == DEPTH - 1);
                #pragma unroll
                for (int c = 0; c < 32; ++c) {
                    float2 vv = lastLayer ? s[c]
                              : cmul(s[c], PostT[dp * 16 + (c & 15)]);
                    u32 a = pb;
                    if (c & 1)  a ^= qd[0];
                    if (c & 2)  a ^= qd[1];
                    if (c & 4)  a ^= qd[2];
                    if (c & 8)  a ^= qd[3];
                    if (c & 16) a ^= qd[4];
                    sv[a] = vv;
                }
                __syncthreads();
            }
        }
    }

    // ---- block reduction -> out[bid] ----
    #pragma unroll
    for (int o = 16; o; o >>= 1) acc += __shfl_xor_sync(0xffffffffu, acc, o);
    if ((t & 31) == 0) red[t >> 5] = acc;
    __syncthreads();
    if (t == 0)
        out[bid] = (red[0] + red[1] + red[2] + red[3]) * (1.0f / NQ);
}

extern "C" void kernel_launch(void* const* d_in, const int* in_sizes, int n_in,
                              void* d_out, int out_size)
{
    const float *inp, *wp;
    if (in_sizes[0] == DEPTH * NQ * 3) {            // defensive input-order check
        wp  = (const float*)d_in[0];
        inp = (const float*)d_in[1];
    } else {
        inp = (const float*)d_in[0];
        wp  = (const float*)d_in[1];
    }
    int B = out_size;                                // [B,1] float output
    qsim_kernel<<<B, TPB>>>(inp, wp, (float*)d_out);
}